// round 1
// baseline (speedup 1.0000x reference)
#include <cuda_runtime.h>
#include <cstdint>

#define NN 512
#define TT 512
#define BB 256

// Rank-2 factorization of W_rec: W_rec[n][k] = q0[n]*V0[k] + q1[n]*V1[k]
__device__ float g_q0[NN];
__device__ float g_q1[NN];
__device__ float g_V0[NN];
__device__ float g_V1[NN];

// ---------------------------------------------------------------------------
// Prep kernel: pivoted Gram-Schmidt rank-2 factorization of W (N x N, row-major)
// One CTA, NN threads. Thread t owns column t (and row t where needed).
// ---------------------------------------------------------------------------
__global__ void __launch_bounds__(NN) prep_kernel(const float* __restrict__ W) {
    __shared__ float sh_q0[NN];
    __shared__ float sh_q1[NN];
    __shared__ float sh_d0[NN];
    __shared__ float red_v[NN];
    __shared__ int   red_i[NN];

    const int t = threadIdx.x;

    // Pass 1: column norms^2 (coalesced: all threads read row i together)
    float a0 = 0.f, a1 = 0.f, a2 = 0.f, a3 = 0.f;
    for (int i = 0; i < NN; i += 4) {
        float w0 = W[(i + 0) * NN + t];
        float w1 = W[(i + 1) * NN + t];
        float w2 = W[(i + 2) * NN + t];
        float w3 = W[(i + 3) * NN + t];
        a0 = fmaf(w0, w0, a0); a1 = fmaf(w1, w1, a1);
        a2 = fmaf(w2, w2, a2); a3 = fmaf(w3, w3, a3);
    }
    const float nrm2 = (a0 + a1) + (a2 + a3);

    // argmax column norm -> pivot j0
    red_v[t] = nrm2; red_i[t] = t;
    __syncthreads();
    for (int off = NN / 2; off > 0; off >>= 1) {
        if (t < off) {
            if (red_v[t + off] > red_v[t]) {
                red_v[t] = red_v[t + off];
                red_i[t] = red_i[t + off];
            }
        }
        __syncthreads();
    }
    const int   j0 = red_i[0];
    const float n0 = red_v[0];

    // q0 = W[:, j0] / ||.||   (thread t handles row t)
    const float inv0 = rsqrtf(n0);
    sh_q0[t] = W[t * NN + j0] * inv0;
    __syncthreads();

    // Pass 2: d0[t] = q0 . W[:,t]  (this is also V0[t]); residual norms
    float d0a = 0.f, d0b = 0.f, d0c = 0.f, d0d = 0.f;
    for (int i = 0; i < NN; i += 4) {
        d0a = fmaf(sh_q0[i + 0], W[(i + 0) * NN + t], d0a);
        d0b = fmaf(sh_q0[i + 1], W[(i + 1) * NN + t], d0b);
        d0c = fmaf(sh_q0[i + 2], W[(i + 2) * NN + t], d0c);
        d0d = fmaf(sh_q0[i + 3], W[(i + 3) * NN + t], d0d);
    }
    const float d0 = (d0a + d0b) + (d0c + d0d);
    sh_d0[t] = d0;
    const float resid = nrm2 - d0 * d0;

    red_v[t] = resid; red_i[t] = t;
    __syncthreads();
    for (int off = NN / 2; off > 0; off >>= 1) {
        if (t < off) {
            if (red_v[t + off] > red_v[t]) {
                red_v[t] = red_v[t + off];
                red_i[t] = red_i[t + off];
            }
        }
        __syncthreads();
    }
    const int   j1  = red_i[0];
    const float r1v = red_v[0];

    // q1 = normalize(W[:,j1] - (q0 . W[:,j1]) q0); note ||.||^2 == resid[j1]
    const float d0j1 = sh_d0[j1];
    const float inv1 = rsqrtf(fmaxf(r1v, 1e-30f));
    const float q1t  = (W[t * NN + j1] - d0j1 * sh_q0[t]) * inv1;
    sh_q1[t] = q1t;

    g_q0[t] = sh_q0[t];
    g_q1[t] = q1t;
    g_V0[t] = d0;
    __syncthreads();

    // Pass 3: V1[t] = q1 . W[:,t]
    float v1a = 0.f, v1b = 0.f, v1c = 0.f, v1d = 0.f;
    for (int i = 0; i < NN; i += 4) {
        v1a = fmaf(sh_q1[i + 0], W[(i + 0) * NN + t], v1a);
        v1b = fmaf(sh_q1[i + 1], W[(i + 1) * NN + t], v1b);
        v1c = fmaf(sh_q1[i + 2], W[(i + 2) * NN + t], v1c);
        v1d = fmaf(sh_q1[i + 3], W[(i + 3) * NN + t], v1d);
    }
    g_V1[t] = (v1a + v1b) + (v1c + v1d);
}

// ---------------------------------------------------------------------------
// Scan kernel: one warp per batch element. Lane L owns state elements
// n in [L*16, L*16+16). Rank-2 recurrence, shuffle reduction, float4 I/O,
// one-step-ahead noise prefetch.
// ---------------------------------------------------------------------------
__global__ void __launch_bounds__(32) scan_kernel(
    const float* __restrict__ u,
    const float* __restrict__ inoise,
    const float* __restrict__ rnoise,
    const float* __restrict__ Win,
    const float* __restrict__ brec,
    float* __restrict__ out)
{
    const int b    = blockIdx.x;
    const int lane = threadIdx.x;
    const int nb   = lane * 16;

    const float ALPHA = 0.2f;
    const float OMA   = 0.8f;
    const float IN_SCALE = 0.6324555320336759f;  // sqrt(2/alpha * sigma_in^2)

    float s[16], V0r[16], V1r[16], U0r[16], U1r[16], W0r[16], W1r[16], br[16];
#pragma unroll
    for (int k = 0; k < 16; k++) {
        const int n = nb + k;
        s[k]   = 0.f;
        V0r[k] = g_V0[n];
        V1r[k] = g_V1[n];
        U0r[k] = g_q0[n];
        U1r[k] = g_q1[n];
        W0r[k] = Win[n * 2 + 0];
        W1r[k] = Win[n * 2 + 1];
        br[k]  = brec[n];
    }

    float* outb = out + (size_t)b * TT * NN;
    // t = 0 state is zeros
    {
        const float4 z = make_float4(0.f, 0.f, 0.f, 0.f);
#pragma unroll
        for (int q = 0; q < 4; q++)
            *reinterpret_cast<float4*>(outb + nb + q * 4) = z;
    }

    const float* rn_b = rnoise + (size_t)b * TT * NN + nb;
    const float* u_b  = u      + (size_t)b * TT * 2;
    const float* in_b = inoise + (size_t)b * TT * 2;

    // Prefetch t = 0 inputs
    float nz[16];
#pragma unroll
    for (int q = 0; q < 4; q++)
        *reinterpret_cast<float4*>(&nz[q * 4]) =
            *reinterpret_cast<const float4*>(rn_b + q * 4);
    float cu0 = fmaf(IN_SCALE, in_b[0], u_b[0]);
    float cu1 = fmaf(IN_SCALE, in_b[1], u_b[1]);

    for (int t = 0; t < TT - 1; t++) {
        // Partial projections p = V * relu(s)
        float p0a = 0.f, p0b = 0.f, p1a = 0.f, p1b = 0.f;
#pragma unroll
        for (int k = 0; k < 16; k += 2) {
            const float r0 = fmaxf(s[k], 0.f);
            const float r1 = fmaxf(s[k + 1], 0.f);
            p0a = fmaf(V0r[k],     r0, p0a);
            p1a = fmaf(V1r[k],     r0, p1a);
            p0b = fmaf(V0r[k + 1], r1, p0b);
            p1b = fmaf(V1r[k + 1], r1, p1b);
        }
        float p0 = p0a + p0b;
        float p1 = p1a + p1b;

        // Prefetch next step's inputs while the reduction chain runs
        float nzn[16];
        float cu0n = 0.f, cu1n = 0.f;
        if (t + 1 < TT - 1) {
            const float* rn_t = rn_b + (size_t)(t + 1) * NN;
#pragma unroll
            for (int q = 0; q < 4; q++)
                *reinterpret_cast<float4*>(&nzn[q * 4]) =
                    *reinterpret_cast<const float4*>(rn_t + q * 4);
            cu0n = fmaf(IN_SCALE, in_b[(t + 1) * 2 + 0], u_b[(t + 1) * 2 + 0]);
            cu1n = fmaf(IN_SCALE, in_b[(t + 1) * 2 + 1], u_b[(t + 1) * 2 + 1]);
        }

        // Warp reduction of the two projections
#pragma unroll
        for (int off = 16; off > 0; off >>= 1) {
            p0 += __shfl_xor_sync(0xffffffffu, p0, off);
            p1 += __shfl_xor_sync(0xffffffffu, p1, off);
        }

        // State update + store
        float outv[16];
#pragma unroll
        for (int k = 0; k < 16; k++) {
            const float inp = fmaf(cu0, W0r[k], cu1 * W1r[k]);
            const float rec = fmaf(U0r[k], p0, U1r[k] * p1);
            const float v   = fmaf(OMA, s[k], ALPHA * (rec + br[k] + inp + nz[k]));
            s[k]    = v;
            outv[k] = v;
        }
        float* o = outb + (size_t)(t + 1) * NN + nb;
#pragma unroll
        for (int q = 0; q < 4; q++)
            *reinterpret_cast<float4*>(o + q * 4) =
                *reinterpret_cast<const float4*>(&outv[q * 4]);

#pragma unroll
        for (int k = 0; k < 16; k++) nz[k] = nzn[k];
        cu0 = cu0n;
        cu1 = cu1n;
    }
}

// ---------------------------------------------------------------------------
// kernel_launch: prep (rank-2 factorization) then scan. Both graph-capturable.
// Input order (metadata): u, input_noise, recurrent_noise, W_in, W_rec, b_rec
// ---------------------------------------------------------------------------
extern "C" void kernel_launch(void* const* d_in, const int* in_sizes, int n_in,
                              void* d_out, int out_size) {
    const float* u      = (const float*)d_in[0];
    const float* inoise = (const float*)d_in[1];
    const float* rnoise = (const float*)d_in[2];
    const float* Win    = (const float*)d_in[3];
    const float* Wrec   = (const float*)d_in[4];
    const float* brec   = (const float*)d_in[5];
    float* out = (float*)d_out;

    prep_kernel<<<1, NN>>>(Wrec);
    scan_kernel<<<BB, 32>>>(u, inoise, rnoise, Win, brec, out);
}

// round 2
// speedup vs baseline: 1.7919x; 1.7919x over previous
#include <cuda_runtime.h>
#include <cstdint>

#define NN 512
#define TT 512
#define BB 256

typedef unsigned long long ull;

// Rank-2 factorization of W_rec: W_rec[n][k] = q0[n]*V0[k] + q1[n]*V1[k]
__device__ __align__(16) float g_q0[NN];
__device__ __align__(16) float g_q1[NN];
__device__ __align__(16) float g_V0[NN];
__device__ __align__(16) float g_V1[NN];
__device__ __align__(16) float g_M[NN][2];
__device__ __align__(16) float g_part[2][32][NN];

// ---------------------------------------------------------------------------
// Packed f32x2 helpers (Blackwell FFMA2)
// ---------------------------------------------------------------------------
__device__ __forceinline__ ull fma2(ull a, ull b, ull c) {
    ull d;
    asm("fma.rn.f32x2 %0, %1, %2, %3;" : "=l"(d) : "l"(a), "l"(b), "l"(c));
    return d;
}
__device__ __forceinline__ ull pack2(float lo, float hi) {
    ull d;
    asm("mov.b64 %0, {%1, %2};" : "=l"(d) : "f"(lo), "f"(hi));
    return d;
}
__device__ __forceinline__ float2 unpack2(ull v) {
    float2 r;
    asm("mov.b64 {%0, %1}, %2;" : "=f"(r.x), "=f"(r.y) : "l"(v));
    return r;
}

// Deterministic pseudo-random in [-1, 1]
__device__ __forceinline__ float prnd(unsigned i, unsigned salt) {
    unsigned h = (i + salt) * 2654435761u;
    h ^= h >> 16; h *= 2246822519u; h ^= h >> 13;
    return (float)(int)h * 4.656612875e-10f;
}

// ---------------------------------------------------------------------------
// Prep 1: M = W @ R  (R deterministic pseudo-random N x 2). One warp per row.
// grid 64 x 256 threads = 512 warps.
// ---------------------------------------------------------------------------
__global__ void __launch_bounds__(256) prep_matvec(const float* __restrict__ W) {
    const int warp = blockIdx.x * 8 + (threadIdx.x >> 5);
    const int lane = threadIdx.x & 31;
    const float4* row4 = reinterpret_cast<const float4*>(W + (size_t)warp * NN);
    float m0 = 0.f, m1 = 0.f;
#pragma unroll
    for (int j = 0; j < 4; j++) {
        const int f4 = lane + 32 * j;
        const float4 w = row4[f4];
        const unsigned i0 = 4 * f4;
        m0 += w.x * prnd(i0, 0u) + w.y * prnd(i0 + 1, 0u)
            + w.z * prnd(i0 + 2, 0u) + w.w * prnd(i0 + 3, 0u);
        m1 += w.x * prnd(i0, 77u) + w.y * prnd(i0 + 1, 77u)
            + w.z * prnd(i0 + 2, 77u) + w.w * prnd(i0 + 3, 77u);
    }
#pragma unroll
    for (int off = 16; off > 0; off >>= 1) {
        m0 += __shfl_xor_sync(0xffffffffu, m0, off);
        m1 += __shfl_xor_sync(0xffffffffu, m1, off);
    }
    if (lane == 0) { g_M[warp][0] = m0; g_M[warp][1] = m1; }
}

// ---------------------------------------------------------------------------
// Prep 2: orthonormalize M (Gram-Schmidt on 2 columns). One CTA, 512 threads.
// ---------------------------------------------------------------------------
__device__ __forceinline__ float block_reduce(float v, float* red, int t) {
    red[t] = v;
    __syncthreads();
    for (int off = 256; off > 0; off >>= 1) {
        if (t < off) red[t] += red[t + off];
        __syncthreads();
    }
    const float r = red[0];
    __syncthreads();
    return r;
}

__global__ void __launch_bounds__(NN) prep_ortho() {
    __shared__ float red[NN];
    const int t = threadIdx.x;
    const float m0 = g_M[t][0];
    const float m1 = g_M[t][1];
    const float n0 = block_reduce(m0 * m0, red, t);
    const float q0 = m0 * rsqrtf(fmaxf(n0, 1e-30f));
    const float d  = block_reduce(q0 * m1, red, t);
    const float w1 = m1 - d * q0;
    const float n1 = block_reduce(w1 * w1, red, t);
    const float q1 = w1 * rsqrtf(fmaxf(n1, 1e-30f));
    g_q0[t] = q0;
    g_q1[t] = q1;
}

// ---------------------------------------------------------------------------
// Prep 3: row-split partials of V = Q^T W.  Grid 32 CTAs x 512 threads.
// CTA c handles rows [c*16, c*16+16); thread t = column.
// ---------------------------------------------------------------------------
__global__ void __launch_bounds__(NN) prep_proj(const float* __restrict__ W) {
    const int c = blockIdx.x;
    const int t = threadIdx.x;
    float a0 = 0.f, a1 = 0.f;
#pragma unroll
    for (int j = 0; j < 16; j++) {
        const int i = c * 16 + j;
        const float w = W[(size_t)i * NN + t];
        a0 = fmaf(g_q0[i], w, a0);
        a1 = fmaf(g_q1[i], w, a1);
    }
    g_part[0][c][t] = a0;
    g_part[1][c][t] = a1;
}

// ---------------------------------------------------------------------------
// Prep 4: reduce partials into V0, V1. One CTA, 512 threads.
// ---------------------------------------------------------------------------
__global__ void __launch_bounds__(NN) prep_reduce() {
    const int t = threadIdx.x;
    float v0 = 0.f, v1 = 0.f;
#pragma unroll
    for (int c = 0; c < 32; c++) {
        v0 += g_part[0][c][t];
        v1 += g_part[1][c][t];
    }
    g_V0[t] = v0;
    g_V1[t] = v1;
}

// ---------------------------------------------------------------------------
// Scan kernel: one warp per batch element. Lane owns 16 state elements
// (8 f32x2 pairs). 4-stage cp.async smem ring for recurrent noise
// (prefetch distance 3). Packed FFMA2 math. Streaming v2.b64 stores.
// ---------------------------------------------------------------------------
#define STAGES 4

__global__ void __launch_bounds__(32) scan_kernel(
    const float* __restrict__ u,
    const float* __restrict__ inoise,
    const float* __restrict__ rnoise,
    const float* __restrict__ Win,
    const float* __restrict__ brec,
    float* __restrict__ out)
{
    __shared__ ulonglong2 ring[STAGES * 128];
    __shared__ float2 cu_sm[TT];

    const int b    = blockIdx.x;
    const int lane = threadIdx.x;
    const int nb   = lane * 16;

    const float ALPHA    = 0.2f;
    const float IN_SCALE = 0.6324555320336759f;  // sqrt(2/alpha * sigma_in^2)

    // ---- precompute alpha * (u + c*inoise) into smem: 1024 floats ----
    {
        const float4* u4 = reinterpret_cast<const float4*>(u + (size_t)b * TT * 2);
        const float4* n4 = reinterpret_cast<const float4*>(inoise + (size_t)b * TT * 2);
        float4* cu4 = reinterpret_cast<float4*>(cu_sm);
#pragma unroll
        for (int j = 0; j < 8; j++) {
            const int i = lane + 32 * j;
            const float4 a = u4[i];
            const float4 c = n4[i];
            float4 o;
            o.x = ALPHA * fmaf(IN_SCALE, c.x, a.x);
            o.y = ALPHA * fmaf(IN_SCALE, c.y, a.y);
            o.z = ALPHA * fmaf(IN_SCALE, c.z, a.z);
            o.w = ALPHA * fmaf(IN_SCALE, c.w, a.w);
            cu4[i] = o;
        }
    }

    // ---- packed per-lane constants (pair p covers elements nb+2p, nb+2p+1) ----
    ull sp[8], V0p[8], V1p[8], AU0p[8], AU1p[8], W0p[8], W1p[8], Abr[8];
    {
        const float2* V02 = reinterpret_cast<const float2*>(g_V0);
        const float2* V12 = reinterpret_cast<const float2*>(g_V1);
        const float2* q02 = reinterpret_cast<const float2*>(g_q0);
        const float2* q12 = reinterpret_cast<const float2*>(g_q1);
        const float2* br2 = reinterpret_cast<const float2*>(brec);
        const float4* Wi4 = reinterpret_cast<const float4*>(Win);
#pragma unroll
        for (int p = 0; p < 8; p++) {
            const int pi = lane * 8 + p;          // pair index in [0, 256)
            sp[p] = 0ull;
            const float2 v0 = V02[pi];
            const float2 v1 = V12[pi];
            const float2 q0 = q02[pi];
            const float2 q1 = q12[pi];
            const float2 br = br2[pi];
            const float4 wi = Wi4[pi];            // (W0[e0], W1[e0], W0[e1], W1[e1])
            V0p[p]  = pack2(v0.x, v0.y);
            V1p[p]  = pack2(v1.x, v1.y);
            AU0p[p] = pack2(ALPHA * q0.x, ALPHA * q0.y);
            AU1p[p] = pack2(ALPHA * q1.x, ALPHA * q1.y);
            W0p[p]  = pack2(wi.x, wi.z);
            W1p[p]  = pack2(wi.y, wi.w);
            Abr[p]  = pack2(ALPHA * br.x, ALPHA * br.y);
        }
    }
    const ull OMA2   = pack2(0.8f, 0.8f);
    const ull ALPHA2 = pack2(0.2f, 0.2f);

    __syncwarp();  // cu_sm visible

    float* outb = out + (size_t)b * TT * NN;
    // t = 0 state is zeros
    {
        const ull z = 0ull;
#pragma unroll
        for (int h = 0; h < 4; h++)
            asm volatile("st.global.cs.v2.b64 [%0], {%1, %2};"
                         :: "l"(outb + nb + h * 4), "l"(z), "l"(z) : "memory");
    }

    // ---- cp.async ring: each lane copies its own 4 float4s per stage ----
    const float* rn_lane = rnoise + (size_t)b * TT * NN + nb;
    const uint32_t ring_base =
        (uint32_t)__cvta_generic_to_shared(ring);

#define ISSUE_STAGE(tt)                                                        \
    do {                                                                       \
        const int _st = (tt) & (STAGES - 1);                                   \
        const float* _g = rn_lane + (size_t)(tt) * NN;                         \
        _Pragma("unroll")                                                      \
        for (int _q = 0; _q < 4; _q++) {                                       \
            const uint32_t _sa = ring_base +                                   \
                ((_st * 128 + _q * 32 + lane) << 4);                           \
            asm volatile("cp.async.cg.shared.global [%0], [%1], 16;"           \
                         :: "r"(_sa), "l"(_g + _q * 4) : "memory");            \
        }                                                                      \
    } while (0)

    ISSUE_STAGE(0);
    asm volatile("cp.async.commit_group;" ::: "memory");
    ISSUE_STAGE(1);
    asm volatile("cp.async.commit_group;" ::: "memory");
    ISSUE_STAGE(2);
    asm volatile("cp.async.commit_group;" ::: "memory");

    for (int t = 0; t < TT - 1; t++) {
        // prefetch stage t+3 (empty commit keeps group accounting uniform)
        if (t + 3 < TT - 1) ISSUE_STAGE(t + 3);
        asm volatile("cp.async.commit_group;" ::: "memory");
        asm volatile("cp.async.wait_group 3;" ::: "memory");

        // per-step scalars (broadcast smem read, issued early)
        const float2 cu = cu_sm[t];

        // noise for this step (conflict-free: slot q*32+lane)
        const int st = t & (STAGES - 1);
        ulonglong2 nzq0 = ring[st * 128 + 0 * 32 + lane];
        ulonglong2 nzq1 = ring[st * 128 + 1 * 32 + lane];
        ulonglong2 nzq2 = ring[st * 128 + 2 * 32 + lane];
        ulonglong2 nzq3 = ring[st * 128 + 3 * 32 + lane];

        // partial projections p = V . relu(s), packed
        ull p0acc = 0ull, p1acc = 0ull;
#pragma unroll
        for (int p = 0; p < 8; p++) {
            const float2 sv = unpack2(sp[p]);
            const ull rp = pack2(fmaxf(sv.x, 0.f), fmaxf(sv.y, 0.f));
            p0acc = fma2(V0p[p], rp, p0acc);
            p1acc = fma2(V1p[p], rp, p1acc);
        }
        const float2 a0 = unpack2(p0acc);
        const float2 a1 = unpack2(p1acc);
        float p0 = a0.x + a0.y;
        float p1 = a1.x + a1.y;

        // warp reduction
#pragma unroll
        for (int off = 16; off > 0; off >>= 1) {
            p0 += __shfl_xor_sync(0xffffffffu, p0, off);
            p1 += __shfl_xor_sync(0xffffffffu, p1, off);
        }

        const ull p0p  = pack2(p0, p0);
        const ull p1p  = pack2(p1, p1);
        const ull acu0 = pack2(cu.x, cu.x);
        const ull acu1 = pack2(cu.y, cu.y);

        // state update: v = 0.8 s + AU0 p0 + AU1 p1 + acu0 W0 + acu1 W1
        //                 + 0.2 nz + 0.2 br           (6 FMA2 per pair)
        const ull nzp[8] = { nzq0.x, nzq0.y, nzq1.x, nzq1.y,
                             nzq2.x, nzq2.y, nzq3.x, nzq3.y };
#pragma unroll
        for (int p = 0; p < 8; p++) {
            ull acc = fma2(ALPHA2, nzp[p], Abr[p]);
            acc = fma2(acu1, W1p[p], acc);
            acc = fma2(acu0, W0p[p], acc);
            acc = fma2(AU1p[p], p1p, acc);
            acc = fma2(AU0p[p], p0p, acc);
            sp[p] = fma2(OMA2, sp[p], acc);
        }

        // streaming store of the new state
        float* o = outb + (size_t)(t + 1) * NN + nb;
#pragma unroll
        for (int h = 0; h < 4; h++)
            asm volatile("st.global.cs.v2.b64 [%0], {%1, %2};"
                         :: "l"(o + h * 4), "l"(sp[2 * h]), "l"(sp[2 * h + 1])
                         : "memory");
    }
#undef ISSUE_STAGE
}

// ---------------------------------------------------------------------------
// kernel_launch. Input order: u, input_noise, recurrent_noise, W_in, W_rec, b_rec
// ---------------------------------------------------------------------------
extern "C" void kernel_launch(void* const* d_in, const int* in_sizes, int n_in,
                              void* d_out, int out_size) {
    const float* u      = (const float*)d_in[0];
    const float* inoise = (const float*)d_in[1];
    const float* rnoise = (const float*)d_in[2];
    const float* Win    = (const float*)d_in[3];
    const float* Wrec   = (const float*)d_in[4];
    const float* brec   = (const float*)d_in[5];
    float* out = (float*)d_out;

    prep_matvec<<<64, 256>>>(Wrec);
    prep_ortho<<<1, NN>>>();
    prep_proj<<<32, NN>>>(Wrec);
    prep_reduce<<<1, NN>>>();
    scan_kernel<<<BB, 32>>>(u, inoise, rnoise, Win, brec, out);
}